// round 17
// baseline (speedup 1.0000x reference)
#include <cuda_runtime.h>
#include <cuda_fp16.h>
#include <cstdint>

#define NE 100000
#define NN 10000
#define KW 1024
#define N3 4096

// ---- static device scratch (no allocations allowed) ----
__device__ __align__(16) __half g_r1[(size_t)NE * KW];   // relu1 [E,1024] fp16 K32-permuted
__device__ __align__(16) __half g_r2[(size_t)NE * KW];   // relu2 [E,1024] fp16 K32-permuted
__device__ __align__(16) __half g_W[(size_t)NE * N3];    // W_edge [E,64,64] fp16 normal
__device__ __align__(16) __half g_Bp2[(size_t)KW * KW];  // k2_w^T [N,K] fp16 K32-permuted
__device__ __align__(16) __half g_Bp3[(size_t)N3 * KW];  // k3_w^T [N,K] fp16 K32-permuted
__device__ float g_hA[NN * 64];
__device__ float g_hB[NN * 64];
__device__ float g_agg[NN * 64];
__device__ float g_inv[NN];

// K-permutation within each 32-group for m16n8k16 fragments (proven layout):
// 4-byte unit = 4t + 2q + hi -> thread t reads 16 contiguous bytes covering
// both k-steps of a BK=32 sub-block. Keeps (2k,2k+1) pairs adjacent.
__device__ __forceinline__ int permk32(int k) {
    return (k & ~31) | (((k >> 1) & 3) << 3) | (((k >> 4) & 1) << 2)
         | (((k >> 3) & 1) << 1) | (k & 1);
}

// fp16 MMA with fp16 accumulator (2 b32 regs = 4 halves)
__device__ __forceinline__ void mma_f16acc(uint32_t* d,
                                           uint32_t a0, uint32_t a1, uint32_t a2, uint32_t a3,
                                           uint32_t b0, uint32_t b1) {
    asm volatile(
        "mma.sync.aligned.m16n8k16.row.col.f16.f16.f16.f16 "
        "{%0,%1}, {%2,%3,%4,%5}, {%6,%7}, {%0,%1};\n"
        : "+r"(d[0]), "+r"(d[1])
        : "r"(a0), "r"(a1), "r"(a2), "r"(a3), "r"(b0), "r"(b1));
}

// ---- B prep: transpose [K,N] -> [N,K], fp16 round, K32-permute ----
__global__ void k_prepB(const float* __restrict__ in, __half* __restrict__ out, int N) {
    __shared__ float tile[32][33];
    int nb = blockIdx.x * 32, kb = blockIdx.y * 32;
    for (int i = threadIdx.y; i < 32; i += 8)
        tile[i][threadIdx.x] = in[(size_t)(kb + i) * N + nb + threadIdx.x];
    __syncthreads();
    for (int i = threadIdx.y; i < 32; i += 8) {
        int n = nb + i, k = kb + threadIdx.x;
        out[(size_t)n * KW + permk32(k)] = __float2half_rn(tile[threadIdx.x][i]);
    }
}

// ---- layer 1 of edge MLP: 2 outputs/thread, half2 permuted write ----
__global__ void k_mlp1(const float* __restrict__ ea, const float* __restrict__ w,
                       const float* __restrict__ b, __half* __restrict__ out) {
    int idx = blockIdx.x * 256 + threadIdx.x;   // grid = NE*2 blocks
    int e = idx >> 9, m = idx & 511;
    int n0 = 2 * m;
    const float* a = ea + e * 6;
    float s0 = b[n0], s1 = b[n0 + 1];
#pragma unroll
    for (int j = 0; j < 6; j++) {
        float av = a[j];
        s0 = fmaf(av, w[j * KW + n0], s0);
        s1 = fmaf(av, w[j * KW + n0 + 1], s1);
    }
    __half2 h2 = __floats2half2_rn(fmaxf(s0, 0.f), fmaxf(s1, 0.f));
    *(__half2*)(out + (size_t)e * KW + permk32(n0)) = h2;
}

// ---- fp16 mma.sync GEMM, fp16 DUAL accumulators: C = A @ Bt^T + bias ----
// CTA tile 128x256, 512 threads = 16 warps (4M x 4N) of 32x64 warp tiles.
// NCH=16 compile-time, 4 stages, compile-time stage rotation.
// Even chunks accumulate into haccE, odd into haccO (f16 chains of 32 HMMA);
// promoted to f32 in the epilogue only.
// mode 1: relu -> fp16 K32-permuted. mode 0: fp16 normal.
#define STG_BYTES 49152   // A: 2x8KB, B: 2x16KB
#define SM_BYTES  (4 * STG_BYTES + 1024)
#define NCH 16

__global__ __launch_bounds__(512, 1)
void k_gemm(const __half* __restrict__ A, const __half* __restrict__ B,
            const float* __restrict__ bias, __half* __restrict__ C,
            int M, int N, int mode) {
    extern __shared__ __align__(16) char smem[];
    const int K = KW;

    const int tid = threadIdx.x;
    const int warp = tid >> 5, lane = tid & 31;
    const int wm = warp & 3, wn = warp >> 2;      // 4M x 4N warps
    const int g = lane >> 2, t = lane & 3;
    const int bN = blockIdx.x, bM = blockIdx.y;

    const __half* Ablk = A + (size_t)bM * 128 * K;
    const __half* Bblk = B + (size_t)bN * 256 * K;

    float* sbias = (float*)(smem + 4 * STG_BYTES);
    if (tid < 256) sbias[tid] = bias[bN * 256 + tid];

    uint32_t haccE[2][8][2] = {}, haccO[2][8][2] = {};

    auto loadChunk = [&](int c, char* stg) {
#pragma unroll
        for (int i = 0; i < 2; i++) {   // A: 2 subs x 128 rows x 4 x 16B
            int idx = tid + i * 512;
            int sub = idx >> 9, rem = idx & 511;
            int row = rem >> 2, j = rem & 3;
            const __half* src = Ablk + (size_t)row * K + c * 64 + sub * 32 + j * 8;
            int pr = (bM * 128 + row < M) ? 16 : 0;
            uint32_t da = (uint32_t)__cvta_generic_to_shared(stg + sub * 8192 + row * 64 + j * 16);
            asm volatile("cp.async.cg.shared.global [%0], [%1], 16, %2;\n"
                         :: "r"(da), "l"(src), "r"(pr));
        }
#pragma unroll
        for (int i = 0; i < 4; i++) {   // B: 2 subs x 256 rows x 4 x 16B
            int idx = tid + i * 512;
            int sub = idx >> 10, rem = idx & 1023;
            int row = rem >> 2, j = rem & 3;
            const __half* src = Bblk + (size_t)row * K + c * 64 + sub * 32 + j * 8;
            uint32_t da = (uint32_t)__cvta_generic_to_shared(stg + 16384 + sub * 16384 + row * 64 + j * 16);
            asm volatile("cp.async.cg.shared.global [%0], [%1], 16;\n"
                         :: "r"(da), "l"(src));
        }
        asm volatile("cp.async.commit_group;\n");
    };

    auto computeChunk = [&](const char* stg, uint32_t (*hacc)[8][2]) {
#pragma unroll
        for (int u = 0; u < 2; u++) {
            const char* As = stg + u * 8192;
            const char* Bs = stg + 16384 + u * 16384;
            uint4 a0[2], a1[2];
#pragma unroll
            for (int mt = 0; mt < 2; mt++) {
                int r = wm * 32 + mt * 16;
                a0[mt] = *(const uint4*)(As + (r + g) * 64 + 16 * t);
                a1[mt] = *(const uint4*)(As + (r + g + 8) * 64 + 16 * t);
            }
#pragma unroll
            for (int nt = 0; nt < 8; nt++) {
                uint4 bv = *(const uint4*)(Bs + (wn * 64 + nt * 8 + g) * 64 + 16 * t);
#pragma unroll
                for (int mt = 0; mt < 2; mt++) {
                    mma_f16acc(hacc[mt][nt], a0[mt].x, a1[mt].x, a0[mt].y, a1[mt].y, bv.x, bv.y);
                    mma_f16acc(hacc[mt][nt], a0[mt].z, a1[mt].z, a0[mt].w, a1[mt].w, bv.z, bv.w);
                }
            }
        }
    };

    loadChunk(0, smem);
    loadChunk(1, smem + STG_BYTES);
    loadChunk(2, smem + 2 * STG_BYTES);

#pragma unroll 1
    for (int c0 = 0; c0 < NCH; c0 += 4) {
#pragma unroll
        for (int ss = 0; ss < 4; ss++) {       // ss compile-time after unroll
            int c = c0 + ss;
            if (c <= NCH - 3)      asm volatile("cp.async.wait_group 2;" ::: "memory");
            else if (c == NCH - 2) asm volatile("cp.async.wait_group 1;" ::: "memory");
            else                   asm volatile("cp.async.wait_group 0;" ::: "memory");
            __syncthreads();
            if (c + 3 < NCH) loadChunk(c + 3, smem + ((ss + 3) & 3) * STG_BYTES);
            computeChunk(smem + ss * STG_BYTES, (ss & 1) ? haccO : haccE);
        }
    }

    // epilogue: promote f16 accs to f32, bias (+relu), fp16 stores
#pragma unroll
    for (int mt = 0; mt < 2; mt++) {
#pragma unroll
        for (int nt = 0; nt < 8; nt++) {
            float2 e0 = __half22float2(*(__half2*)&haccE[mt][nt][0]);
            float2 e1 = __half22float2(*(__half2*)&haccE[mt][nt][1]);
            float2 o0 = __half22float2(*(__half2*)&haccO[mt][nt][0]);
            float2 o1 = __half22float2(*(__half2*)&haccO[mt][nt][1]);
            int lc = wn * 64 + nt * 8 + 2 * t;
            int col = bN * 256 + lc;
            float b0 = sbias[lc], b1 = sbias[lc + 1];
            int r0 = bM * 128 + wm * 32 + mt * 16 + g;
            int r1 = r0 + 8;
            float v0 = e0.x + o0.x + b0, v1 = e0.y + o0.y + b1;
            float v2 = e1.x + o1.x + b0, v3 = e1.y + o1.y + b1;
            int oc;
            if (mode == 1) {
                v0 = fmaxf(v0, 0.f); v1 = fmaxf(v1, 0.f);
                v2 = fmaxf(v2, 0.f); v3 = fmaxf(v3, 0.f);
                oc = permk32(col);
            } else {
                oc = col;
            }
            __half2 h01 = __floats2half2_rn(v0, v1);
            __half2 h23 = __floats2half2_rn(v2, v3);
            if (r0 < M) *(__half2*)(C + (size_t)r0 * N + oc) = h01;
            if (r1 < M) *(__half2*)(C + (size_t)r1 * N + oc) = h23;
        }
    }
}

// ---- in-degree via atomics (edge_index is int32: JAX downcasts int64) ----
__global__ void k_deg(const int* __restrict__ ei, float* __restrict__ deg) {
    int i = blockIdx.x * 256 + threadIdx.x;
    if (i < NE) atomicAdd(&deg[ei[NE + i]], 1.f);
}
__global__ void k_inv(float* __restrict__ deg) {
    int n = blockIdx.x * 256 + threadIdx.x;
    if (n < NN) { float d = deg[n]; deg[n] = (d > 0.f) ? (1.f / d) : 0.f; }
}

// ---- h0 = x @ fc1_w + fc1_b (IN_WIDTH = 1) ----
__global__ void k_h0(const float* __restrict__ x, const float* __restrict__ w,
                     const float* __restrict__ b, float* __restrict__ h) {
    int idx = blockIdx.x * 256 + threadIdx.x;
    int n = idx >> 6, o = idx & 63;
    h[idx] = fmaf(x[n], w[o], b[o]);
}

// ---- per-edge matvec + scatter-add: one warp per edge, half2 W ----
__global__ __launch_bounds__(256)
void k_edge(const float* __restrict__ h, const __half* __restrict__ W,
            const int* __restrict__ ei, float* __restrict__ agg) {
    int warp = threadIdx.x >> 5, lane = threadIdx.x & 31;
    int e = blockIdx.x * 8 + warp;             // NE divisible by 8
    int src = ei[e], dst = ei[NE + e];
    __shared__ float sh[8][64];
    float2 hv = ((const float2*)(h + (size_t)src * 64))[lane];
    sh[warp][2 * lane] = hv.x;
    sh[warp][2 * lane + 1] = hv.y;
    __syncwarp();
    const uint32_t* Wr = (const uint32_t*)(W + (size_t)e * 4096);
    float m0 = 0.f, m1 = 0.f;
#pragma unroll 16
    for (int c = 0; c < 64; c++) {
        float hc = sh[warp][c];
        uint32_t wv = __ldg(&Wr[c * 32 + lane]);
        float2 wf = __half22float2(*(__half2*)&wv);
        m0 = fmaf(hc, wf.x, m0);
        m1 = fmaf(hc, wf.y, m1);
    }
    atomicAdd(&agg[dst * 64 + 2 * lane], m0);
    atomicAdd(&agg[dst * 64 + 2 * lane + 1], m1);
}

// ---- h_new = agg*inv_deg + h@root + conv_b (+relu); zeroes agg for next pass ----
__global__ void k_update(const float* __restrict__ hin, float* __restrict__ agg,
                         const float* __restrict__ inv, const float* __restrict__ root,
                         const float* __restrict__ cb, float* __restrict__ hout, int relu) {
    int ni = threadIdx.x >> 6;
    int node = blockIdx.x * 4 + ni;
    int o = threadIdx.x & 63;
    __shared__ float sh[4][64];
    sh[ni][o] = hin[node * 64 + o];
    __syncthreads();
    float av = agg[node * 64 + o];
    agg[node * 64 + o] = 0.f;                  // reset for next depth's atomics
    float acc = fmaf(av, inv[node], cb[o]);
#pragma unroll
    for (int c = 0; c < 64; c++) acc = fmaf(sh[ni][c], root[c * 64 + o], acc);
    if (relu) acc = fmaxf(acc, 0.f);
    hout[node * 64 + o] = acc;
}

// ---- out = h @ fc2_w + fc2_b : one warp per node ----
__global__ void k_final(const float* __restrict__ h, const float* __restrict__ w,
                        const float* __restrict__ b, float* __restrict__ out) {
    int node = blockIdx.x * 8 + (threadIdx.x >> 5);
    int lane = threadIdx.x & 31;
    float v = h[node * 64 + lane] * w[lane] + h[node * 64 + 32 + lane] * w[32 + lane];
#pragma unroll
    for (int s = 16; s > 0; s >>= 1) v += __shfl_xor_sync(0xffffffffu, v, s);
    if (lane == 0) out[node] = v + b[0];
}

extern "C" void kernel_launch(void* const* d_in, const int* in_sizes, int n_in,
                              void* d_out, int out_size) {
    const float* x    = (const float*)d_in[0];
    const int*   ei   = (const int*)d_in[1];     // int32
    const float* ea   = (const float*)d_in[2];
    const float* fc1w = (const float*)d_in[3];
    const float* fc1b = (const float*)d_in[4];
    const float* k1w  = (const float*)d_in[5];
    const float* k1b  = (const float*)d_in[6];
    const float* k2w  = (const float*)d_in[7];
    const float* k2b  = (const float*)d_in[8];
    const float* k3w  = (const float*)d_in[9];
    const float* k3b  = (const float*)d_in[10];
    const float* root = (const float*)d_in[11];
    const float* cb   = (const float*)d_in[12];
    const float* fc2w = (const float*)d_in[13];
    const float* fc2b = (const float*)d_in[14];
    float* out = (float*)d_out;

    __half *r1, *r2, *Wd, *Bp2, *Bp3;
    float *hA, *hB, *agg, *inv;
    cudaGetSymbolAddress((void**)&r1,  g_r1);
    cudaGetSymbolAddress((void**)&r2,  g_r2);
    cudaGetSymbolAddress((void**)&Wd,  g_W);
    cudaGetSymbolAddress((void**)&Bp2, g_Bp2);
    cudaGetSymbolAddress((void**)&Bp3, g_Bp3);
    cudaGetSymbolAddress((void**)&hA,  g_hA);
    cudaGetSymbolAddress((void**)&hB,  g_hB);
    cudaGetSymbolAddress((void**)&agg, g_agg);
    cudaGetSymbolAddress((void**)&inv, g_inv);

    cudaFuncSetAttribute(k_gemm, cudaFuncAttributeMaxDynamicSharedMemorySize, SM_BYTES);

    // weight prep: transpose to [N,K] + fp16 round + K32-permute
    k_prepB<<<dim3(KW / 32, KW / 32), dim3(32, 8)>>>(k2w, Bp2, KW);
    k_prepB<<<dim3(N3 / 32, KW / 32), dim3(32, 8)>>>(k3w, Bp3, N3);

    // edge MLP
    k_mlp1<<<NE * 2, 256>>>(ea, k1w, k1b, r1);
    dim3 g2(KW / 256, (NE + 127) / 128);   // x = N-blocks (fast) for L2 A/B reuse
    dim3 g3(N3 / 256, (NE + 127) / 128);
    k_gemm<<<g2, 512, SM_BYTES>>>(r1, Bp2, k2b, r2, NE, KW, 1);
    k_gemm<<<g3, 512, SM_BYTES>>>(r2, Bp3, k3b, Wd, NE, N3, 0);

    // degrees
    cudaMemsetAsync(inv, 0, NN * sizeof(float));
    k_deg<<<(NE + 255) / 256, 256>>>(ei, inv);
    k_inv<<<(NN + 255) / 256, 256>>>(inv);

    // initial features + one-time agg zero (k_update re-zeroes thereafter)
    k_h0<<<(NN * 64) / 256, 256>>>(x, fc1w, fc1b, hA);
    cudaMemsetAsync(agg, 0, (size_t)NN * 64 * sizeof(float));

    float* hc = hA;
    float* hn = hB;
    for (int d = 0; d < 6; d++) {
        k_edge<<<NE / 8, 256>>>(hc, Wd, ei, agg);
        k_update<<<NN / 4, 256>>>(hc, agg, inv, root, cb, hn, d < 5 ? 1 : 0);
        float* tmp = hc; hc = hn; hn = tmp;
    }

    k_final<<<NN / 8, 256>>>(hc, fc2w, fc2b, out);
}